// round 5
// baseline (speedup 1.0000x reference)
#include <cuda_runtime.h>
#include <math.h>

#define B 64
#define N 4096
#define D 256
#define S 8
#define NP 16
#define RPW 64
#define SC_LOG2E 0.09016844196f   // (1/16) * log2(e)

typedef unsigned long long u64;

// ---- scratch (device globals) ----
__device__ float g_slots[B * S * D];
__device__ float g_qg[B * S * D];
__device__ float g_cm[B * S];
__device__ float g_Up[(size_t)NP * B * S * D];
__device__ float g_hs[(size_t)NP * B * D];
__device__ float g_z[NP * B * S];
// transposed weights WT[d][r]
__device__ float g_WqT[D * D];
__device__ float g_WvT[D * D];
__device__ float g_W1T[D * D];
__device__ float g_W2T[D * D];
__device__ float g_WihT[D * 3 * D];
__device__ float g_WhhT[D * 3 * D];

__device__ __forceinline__ float warp_sum(float v) {
    #pragma unroll
    for (int o = 16; o > 0; o >>= 1) v += __shfl_xor_sync(0xffffffffu, v, o);
    return v;
}
__device__ __forceinline__ float ex2f(float v) {
    float r; asm("ex2.approx.f32 %0, %1;" : "=f"(r) : "f"(v)); return r;
}
// ---- packed f32x2 helpers ----
__device__ __forceinline__ u64 pk2(float lo, float hi) {
    u64 r; asm("mov.b64 %0, {%1, %2};" : "=l"(r) : "f"(lo), "f"(hi)); return r;
}
__device__ __forceinline__ void upk2(u64 v, float& lo, float& hi) {
    asm("mov.b64 {%0, %1}, %2;" : "=f"(lo), "=f"(hi) : "l"(v));
}
__device__ __forceinline__ u64 fma2(u64 a, u64 b, u64 c) {
    u64 d; asm("fma.rn.f32x2 %0, %1, %2, %3;" : "=l"(d) : "l"(a), "l"(b), "l"(c)); return d;
}
__device__ __forceinline__ u64 add2(u64 a, u64 b) {
    u64 d; asm("add.rn.f32x2 %0, %1, %2;" : "=l"(d) : "l"(a), "l"(b)); return d;
}
__device__ __forceinline__ u64 mul2(u64 a, u64 b) {
    u64 d; asm("mul.rn.f32x2 %0, %1, %2;" : "=l"(d) : "l"(a), "l"(b)); return d;
}

// LayerNorm one row of 256 floats, one warp.
__device__ __forceinline__ void ln_row_warp(const float* __restrict__ src,
                                            float* __restrict__ dst,
                                            const float* __restrict__ g,
                                            const float* __restrict__ be,
                                            int lane) {
    float4 a = ((const float4*)src)[lane];
    float4 c = ((const float4*)src)[lane + 32];
    float s = a.x + a.y + a.z + a.w + c.x + c.y + c.z + c.w;
    float q = a.x * a.x + a.y * a.y + a.z * a.z + a.w * a.w
            + c.x * c.x + c.y * c.y + c.z * c.z + c.w * c.w;
    s = warp_sum(s);
    q = warp_sum(q);
    float mu = s * (1.0f / 256.0f);
    float var = q * (1.0f / 256.0f) - mu * mu;
    float rs = rsqrtf(var + 1e-5f);
    float4 g0 = ((const float4*)g)[lane], g1 = ((const float4*)g)[lane + 32];
    float4 e0 = ((const float4*)be)[lane], e1 = ((const float4*)be)[lane + 32];
    float4 o0, o1;
    o0.x = (a.x - mu) * rs * g0.x + e0.x;
    o0.y = (a.y - mu) * rs * g0.y + e0.y;
    o0.z = (a.z - mu) * rs * g0.z + e0.z;
    o0.w = (a.w - mu) * rs * g0.w + e0.w;
    o1.x = (c.x - mu) * rs * g1.x + e1.x;
    o1.y = (c.y - mu) * rs * g1.y + e1.y;
    o1.z = (c.z - mu) * rs * g1.z + e1.z;
    o1.w = (c.w - mu) * rs * g1.w + e1.w;
    ((float4*)dst)[lane] = o0;
    ((float4*)dst)[lane + 32] = o1;
}

// ---------------- transpose all weights (one-time per launch) ----------------
__global__ __launch_bounds__(256) void transpose_all(const float* __restrict__ Wq,
                                                     const float* __restrict__ Wv,
                                                     const float* __restrict__ W1,
                                                     const float* __restrict__ W2,
                                                     const float* __restrict__ Wih,
                                                     const float* __restrict__ Whh) {
    __shared__ float t[32][33];
    int m = blockIdx.y;
    const float* src; float* dst; int R;
    switch (m) {
        case 0: src = Wq;  dst = g_WqT;  R = 256; break;
        case 1: src = Wv;  dst = g_WvT;  R = 256; break;
        case 2: src = W1;  dst = g_W1T;  R = 256; break;
        case 3: src = W2;  dst = g_W2T;  R = 256; break;
        case 4: src = Wih; dst = g_WihT; R = 768; break;
        default: src = Whh; dst = g_WhhT; R = 768; break;
    }
    int tiles_x = 256 / 32;
    int ntiles = (R / 32) * tiles_x;
    if (blockIdx.x >= (unsigned)ntiles) return;
    int tx = blockIdx.x % tiles_x;   // over d
    int ty = blockIdx.x / tiles_x;   // over r
    int lx = threadIdx.x & 31, ly = threadIdx.x >> 5;
    #pragma unroll
    for (int i = 0; i < 4; i++)
        t[ly + i * 8][lx] = src[(size_t)(ty * 32 + ly + i * 8) * 256 + tx * 32 + lx];
    __syncthreads();
    #pragma unroll
    for (int i = 0; i < 4; i++)
        dst[(size_t)(tx * 32 + ly + i * 8) * R + ty * 32 + lx] = t[lx][ly + i * 8];
}

// ---------------- slots init ----------------
__global__ __launch_bounds__(256) void init_slots_kernel(const float* __restrict__ noise,
                                                         const float* __restrict__ mu,
                                                         const float* __restrict__ ls) {
    int i = blockIdx.x * 256 + threadIdx.x;
    int d = i & (D - 1);
    g_slots[i] = mu[d] + noise[i] * expf(ls[d]);
}

// ---------------- qproj tail: g_qg, g_cm for 4 slots ----------------
__device__ __forceinline__ void qproj_tail(const float* fin, float* sln, float* qb,
                                           float* red, int b, int sb, int tid,
                                           const float* __restrict__ Wk,
                                           const float* __restrict__ g_sl,
                                           const float* __restrict__ be_sl,
                                           const float* __restrict__ gin) {
    int w = tid >> 5, lane = tid & 31;
    if (w < 4) ln_row_warp(fin + w * D, sln + w * D, g_sl, be_sl, lane);
    __syncthreads();
    // q[s][e=tid] = sum_d sln[s][d] * WqT[d][e]
    float acc[4] = {0.f, 0.f, 0.f, 0.f};
    #pragma unroll 4
    for (int d = 0; d < D; d++) {
        float wv = g_WqT[d * D + tid];
        #pragma unroll
        for (int s = 0; s < 4; s++) acc[s] += sln[s * D + d] * wv;
    }
    #pragma unroll
    for (int s = 0; s < 4; s++) qb[s * D + tid] = acc[s];
    __syncthreads();
    // qt[s][d=tid] = sum_e q[s][e] * Wk[e][d]
    float a2[4] = {0.f, 0.f, 0.f, 0.f};
    #pragma unroll 4
    for (int e = 0; e < D; e++) {
        float wv = Wk[(size_t)e * D + tid];
        #pragma unroll
        for (int s = 0; s < 4; s++) a2[s] += qb[s * D + e] * wv;
    }
    float gv = gin[tid];
    float nrm[4];
    #pragma unroll
    for (int s = 0; s < 4; s++) {
        float qv = a2[s] * SC_LOG2E * gv;
        g_qg[(b * S + sb + s) * D + tid] = qv;
        nrm[s] = qv * qv;
    }
    #pragma unroll
    for (int s = 0; s < 4; s++) {
        float v = warp_sum(nrm[s]);
        if (lane == 0) red[s * 8 + w] = v;
    }
    __syncthreads();
    if (tid < 4) {
        float t = 0.f;
        #pragma unroll
        for (int i = 0; i < 8; i++) t += red[tid * 8 + i];
        g_cm[b * S + sb + tid] = -16.0f * sqrtf(t);
    }
}

__global__ __launch_bounds__(256) void qproj0_kernel(const float* __restrict__ Wk,
                                                     const float* __restrict__ g_sl,
                                                     const float* __restrict__ be_sl,
                                                     const float* __restrict__ gin) {
    __shared__ __align__(16) float fin[4 * D], sln[4 * D], qb[4 * D];
    __shared__ float red[32];
    int b = blockIdx.x >> 1, sb = (blockIdx.x & 1) * 4, tid = threadIdx.x;
    for (int i = tid; i < 4 * D; i += 256) fin[i] = g_slots[b * S * D + sb * D + i];
    __syncthreads();
    qproj_tail(fin, sln, qb, red, b, sb, tid, Wk, g_sl, be_sl, gin);
}

// ---------------- fused flash attention (warp-autonomous, f32x2) ----------------
__global__ __launch_bounds__(128) void fused_attn_kernel(const float* __restrict__ x) {
    __shared__ __align__(16) float Usm[4 * S * D];
    __shared__ __align__(16) float hssm[4 * D];
    __shared__ float zsm[4 * S];
    int b = blockIdx.y;
    int wid = threadIdx.x >> 5, lane = threadIdx.x & 31;
    int pidx = blockIdx.x * 4 + wid;
    const float* xb = x + ((size_t)b * N + (size_t)pidx * RPW) * D + lane * 8;

    u64 qg2[S][4];
    #pragma unroll
    for (int s = 0; s < S; s++) {
        float4 a = *(const float4*)&g_qg[(b * S + s) * D + lane * 8];
        float4 c = *(const float4*)&g_qg[(b * S + s) * D + lane * 8 + 4];
        qg2[s][0] = pk2(a.x, a.y); qg2[s][1] = pk2(a.z, a.w);
        qg2[s][2] = pk2(c.x, c.y); qg2[s][3] = pk2(c.z, c.w);
    }
    float cm[S];
    #pragma unroll
    for (int s = 0; s < S; s++) cm[s] = g_cm[b * S + s];

    u64 U2[S][4];
    u64 zero2 = pk2(0.f, 0.f);
    #pragma unroll
    for (int s = 0; s < S; s++)
        #pragma unroll
        for (int k = 0; k < 4; k++) U2[s][k] = zero2;
    u64 hs2[4] = {zero2, zero2, zero2, zero2};
    float z[S];
    #pragma unroll
    for (int s = 0; s < S; s++) z[s] = 0.f;

    float4 pf0 = *(const float4*)xb;
    float4 pf1 = *(const float4*)(xb + 4);

    for (int r = 0; r < RPW; r++) {
        u64 x2[4] = {pk2(pf0.x, pf0.y), pk2(pf0.z, pf0.w),
                     pk2(pf1.x, pf1.y), pk2(pf1.z, pf1.w)};
        if (r + 1 < RPW) {
            const float* nx = xb + (size_t)(r + 1) * D;
            pf0 = *(const float4*)nx;
            pf1 = *(const float4*)(nx + 4);
        }
        // LN sums (packed)
        u64 s1p = x2[0], s2p = mul2(x2[0], x2[0]);
        #pragma unroll
        for (int k = 1; k < 4; k++) {
            s1p = add2(s1p, x2[k]);
            s2p = fma2(x2[k], x2[k], s2p);
        }
        float s1a, s1b, s2a, s2b;
        upk2(s1p, s1a, s1b); upk2(s2p, s2a, s2b);
        float s1 = s1a + s1b, s2 = s2a + s2b;
        #pragma unroll
        for (int o = 16; o > 0; o >>= 1) {
            s1 += __shfl_xor_sync(0xffffffffu, s1, o);
            s2 += __shfl_xor_sync(0xffffffffu, s2, o);
        }
        float mu = s1 * (1.0f / 256.0f);
        float var = fmaf(-mu, mu, s2 * (1.0f / 256.0f));
        float rs = rsqrtf(var + 1e-5f);
        float nb = -mu * rs;
        u64 rs2 = pk2(rs, rs), nb2 = pk2(nb, nb);
        u64 h2[4];
        #pragma unroll
        for (int k = 0; k < 4; k++) h2[k] = fma2(x2[k], rs2, nb2);
        // logits partials
        float p[S];
        #pragma unroll
        for (int s = 0; s < S; s++) {
            u64 a = mul2(qg2[s][0], h2[0]);
            #pragma unroll
            for (int k = 1; k < 4; k++) a = fma2(qg2[s][k], h2[k], a);
            float aa, ab;
            upk2(a, aa, ab);
            p[s] = aa + ab;
        }
        #pragma unroll
        for (int o = 16; o > 0; o >>= 1) {
            #pragma unroll
            for (int s = 0; s < S; s++)
                p[s] += __shfl_xor_sync(0xffffffffu, p[s], o);
        }
        #pragma unroll
        for (int s = 0; s < S; s++) {
            float w = ex2f(p[s] + cm[s]);
            z[s] += w;
            u64 w2 = pk2(w, w);
            #pragma unroll
            for (int k = 0; k < 4; k++) U2[s][k] = fma2(w2, h2[k], U2[s][k]);
        }
        #pragma unroll
        for (int k = 0; k < 4; k++) hs2[k] = add2(hs2[k], h2[k]);
    }

    // block merge
    #pragma unroll
    for (int s = 0; s < S; s++) {
        float u0, u1, u2v, u3, u4, u5, u6, u7;
        upk2(U2[s][0], u0, u1); upk2(U2[s][1], u2v, u3);
        upk2(U2[s][2], u4, u5); upk2(U2[s][3], u6, u7);
        *(float4*)&Usm[(wid * S + s) * D + lane * 8] = make_float4(u0, u1, u2v, u3);
        *(float4*)&Usm[(wid * S + s) * D + lane * 8 + 4] = make_float4(u4, u5, u6, u7);
    }
    {
        float h0, h1, h2v, h3, h4, h5, h6, h7;
        upk2(hs2[0], h0, h1); upk2(hs2[1], h2v, h3);
        upk2(hs2[2], h4, h5); upk2(hs2[3], h6, h7);
        *(float4*)&hssm[wid * D + lane * 8] = make_float4(h0, h1, h2v, h3);
        *(float4*)&hssm[wid * D + lane * 8 + 4] = make_float4(h4, h5, h6, h7);
    }
    if (lane == 0) {
        #pragma unroll
        for (int s = 0; s < S; s++) zsm[wid * S + s] = z[s];
    }
    __syncthreads();
    int tid = threadIdx.x;
    size_t pb = (size_t)blockIdx.x * B + b;
    #pragma unroll
    for (int k = 0; k < S; k++) {
        float a = 0.f, a2 = 0.f;
        #pragma unroll
        for (int w = 0; w < 4; w++) {
            a += Usm[(w * S + k) * D + tid];
            a2 += Usm[(w * S + k) * D + tid + 128];
        }
        g_Up[(pb * S + k) * D + tid] = a;
        g_Up[(pb * S + k) * D + tid + 128] = a2;
    }
    {
        float a = 0.f, a2 = 0.f;
        #pragma unroll
        for (int w = 0; w < 4; w++) { a += hssm[w * D + tid]; a2 += hssm[w * D + tid + 128]; }
        g_hs[pb * D + tid] = a;
        g_hs[pb * D + tid + 128] = a2;
    }
    if (tid < S) {
        float a = 0.f;
        #pragma unroll
        for (int w = 0; w < 4; w++) a += zsm[w * S + tid];
        g_z[pb * S + tid] = a;
    }
}

// ---------------- fused epilogue: reduce + GRU + MLP + next qproj ----------------
__global__ __launch_bounds__(256) void iter_kernel(
    const float* __restrict__ gin, const float* __restrict__ bein,
    const float* __restrict__ bih, const float* __restrict__ bhh,
    const float* __restrict__ b1, const float* __restrict__ b2,
    const float* __restrict__ g_ff, const float* __restrict__ be_ff,
    const float* __restrict__ g_sl, const float* __restrict__ be_sl,
    const float* __restrict__ Wk,
    float* __restrict__ out, int last) {
    __shared__ __align__(16) float upd[4 * D], prev[4 * D], uv[4 * D];
    __shared__ __align__(16) float fin[4 * D], sln[4 * D], qb[4 * D];
    __shared__ float red[32];
    __shared__ float zin[4];
    int b = blockIdx.x >> 1, sb = (blockIdx.x & 1) * 4, tid = threadIdx.x;
    int w = tid >> 5, lane = tid & 31;

    // ---- reduce partials -> updates (x-space), fold LN-out affine ----
    float ua[4] = {0.f, 0.f, 0.f, 0.f};
    #pragma unroll
    for (int p = 0; p < NP; p++) {
        size_t base = ((size_t)p * B + b) * S * D + sb * D;
        #pragma unroll
        for (int s = 0; s < 4; s++) ua[s] += g_Up[base + s * D + tid];
    }
    float hsum = 0.f;
    #pragma unroll
    for (int p = 0; p < NP; p++) hsum += g_hs[((size_t)p * B + b) * D + tid];
    if (tid < 4) {
        float zz = 0.f;
        #pragma unroll
        for (int p = 0; p < NP; p++) zz += g_z[(p * B + b) * S + sb + tid];
        zin[tid] = 1.f / zz;
    }
    for (int i = tid; i < 4 * D; i += 256) prev[i] = g_slots[b * S * D + sb * D + i];
    __syncthreads();
    const float rn = 1.f / (1.f + (float)N * 1e-8f);
    float gv = gin[tid], bv = bein[tid];
    #pragma unroll
    for (int s = 0; s < 4; s++)
        upd[s * D + tid] = gv * ((ua[s] * zin[s] + 1e-8f * hsum) * rn) + bv;
    __syncthreads();
    // ---- uv = updates @ Wv^T (coalesced WvT) ----
    {
        float acc[4] = {0.f, 0.f, 0.f, 0.f};
        #pragma unroll 4
        for (int d = 0; d < D; d++) {
            float wv = g_WvT[d * D + tid];
            #pragma unroll
            for (int s = 0; s < 4; s++) acc[s] += upd[s * D + d] * wv;
        }
        #pragma unroll
        for (int s = 0; s < 4; s++) uv[s * D + tid] = acc[s];
    }
    __syncthreads();
    // ---- GRU (coalesced WihT/WhhT) ----
    {
        float ai0[4] = {0,0,0,0}, ai1[4] = {0,0,0,0}, ai2[4] = {0,0,0,0};
        float ah0[4] = {0,0,0,0}, ah1[4] = {0,0,0,0}, ah2[4] = {0,0,0,0};
        #pragma unroll 2
        for (int d = 0; d < D; d++) {
            const float* wi = &g_WihT[d * 3 * D];
            const float* wh = &g_WhhT[d * 3 * D];
            float wi0 = wi[tid], wi1 = wi[D + tid], wi2 = wi[2 * D + tid];
            float wh0 = wh[tid], wh1 = wh[D + tid], wh2 = wh[2 * D + tid];
            #pragma unroll
            for (int s = 0; s < 4; s++) {
                float u = uv[s * D + d], pv = prev[s * D + d];
                ai0[s] = fmaf(u, wi0, ai0[s]);
                ai1[s] = fmaf(u, wi1, ai1[s]);
                ai2[s] = fmaf(u, wi2, ai2[s]);
                ah0[s] = fmaf(pv, wh0, ah0[s]);
                ah1[s] = fmaf(pv, wh1, ah1[s]);
                ah2[s] = fmaf(pv, wh2, ah2[s]);
            }
        }
        float bi0 = bih[tid], bi1 = bih[D + tid], bi2 = bih[2 * D + tid];
        float bh0 = bhh[tid], bh1 = bhh[D + tid], bh2 = bhh[2 * D + tid];
        #pragma unroll
        for (int s = 0; s < 4; s++) {
            float r = 1.f / (1.f + expf(-(ai0[s] + bi0 + ah0[s] + bh0)));
            float zz = 1.f / (1.f + expf(-(ai1[s] + bi1 + ah1[s] + bh1)));
            float nn = tanhf(ai2[s] + bi2 + r * (ah2[s] + bh2));
            fin[s * D + tid] = (1.f - zz) * nn + zz * prev[s * D + tid];
        }
    }
    __syncthreads();
    // ---- MLP + residual ----
    if (w < 4) ln_row_warp(fin + w * D, sln + w * D, g_ff, be_ff, lane);
    __syncthreads();
    {
        float acc[4] = {0.f, 0.f, 0.f, 0.f};
        #pragma unroll 4
        for (int d = 0; d < D; d++) {
            float wv = g_W1T[d * D + tid];
            #pragma unroll
            for (int s = 0; s < 4; s++) acc[s] += sln[s * D + d] * wv;
        }
        float b1v = b1[tid];
        #pragma unroll
        for (int s = 0; s < 4; s++) qb[s * D + tid] = fmaxf(acc[s] + b1v, 0.f);
    }
    __syncthreads();
    {
        float a2[4] = {0.f, 0.f, 0.f, 0.f};
        #pragma unroll 4
        for (int d = 0; d < D; d++) {
            float wv = g_W2T[d * D + tid];
            #pragma unroll
            for (int s = 0; s < 4; s++) a2[s] += qb[s * D + d] * wv;
        }
        float b2v = b2[tid];
        #pragma unroll
        for (int s = 0; s < 4; s++) {
            float o = fin[s * D + tid] + a2[s] + b2v;
            fin[s * D + tid] = o;
            g_slots[b * S * D + sb * D + s * D + tid] = o;
            if (last) out[b * S * D + sb * D + s * D + tid] = o;
        }
    }
    __syncthreads();
    if (!last)
        qproj_tail(fin, sln, qb, red, b, sb, tid, Wk, g_sl, be_sl, gin);
}

extern "C" void kernel_launch(void* const* d_in, const int* in_sizes, int n_in,
                              void* d_out, int out_size) {
    const float* x        = (const float*)d_in[0];
    const float* noise    = (const float*)d_in[1];
    const float* slots_mu = (const float*)d_in[2];
    const float* slots_ls = (const float*)d_in[3];
    const float* Wq       = (const float*)d_in[4];
    const float* Wk       = (const float*)d_in[5];
    const float* Wv       = (const float*)d_in[6];
    const float* W_ih     = (const float*)d_in[7];
    const float* W_hh     = (const float*)d_in[8];
    const float* b_ih     = (const float*)d_in[9];
    const float* b_hh     = (const float*)d_in[10];
    const float* W1       = (const float*)d_in[11];
    const float* b1       = (const float*)d_in[12];
    const float* W2       = (const float*)d_in[13];
    const float* b2       = (const float*)d_in[14];
    const float* g_in     = (const float*)d_in[15];
    const float* be_in    = (const float*)d_in[16];
    const float* g_sl     = (const float*)d_in[17];
    const float* be_sl    = (const float*)d_in[18];
    const float* g_ff     = (const float*)d_in[19];
    const float* be_ff    = (const float*)d_in[20];
    float* out = (float*)d_out;

    transpose_all<<<dim3(192, 6), 256>>>(Wq, Wv, W1, W2, W_ih, W_hh);
    init_slots_kernel<<<(B * S * D) / 256, 256>>>(noise, slots_mu, slots_ls);
    qproj0_kernel<<<B * 2, 256>>>(Wk, g_sl, be_sl, g_in);
    for (int it = 0; it < 3; it++) {
        fused_attn_kernel<<<dim3(NP, B), 128>>>(x);
        iter_kernel<<<B * 2, 256>>>(g_in, be_in, b_ih, b_hh, b1, b2,
                                    g_ff, be_ff, g_sl, be_sl, Wk,
                                    out, it == 2 ? 1 : 0);
    }
}

// round 6
// speedup vs baseline: 1.9490x; 1.9490x over previous
#include <cuda_runtime.h>
#include <math.h>

#define B 64
#define N 4096
#define D 256
#define S 8
#define NP 16
#define RPW 64
#define SC_LOG2E 0.09016844196f   // (1/16) * log2(e)

typedef unsigned long long u64;

// ---- scratch (device globals) ----
__device__ float g_slots[B * S * D];
__device__ float g_qg[B * S * D];
__device__ float g_cm[B * S];
__device__ float g_Up[(size_t)NP * B * S * D];
__device__ float g_hs[(size_t)NP * B * D];
__device__ float g_z[NP * B * S];

__device__ __forceinline__ float warp_sum(float v) {
    #pragma unroll
    for (int o = 16; o > 0; o >>= 1) v += __shfl_xor_sync(0xffffffffu, v, o);
    return v;
}
__device__ __forceinline__ float ex2f(float v) {
    float r; asm("ex2.approx.f32 %0, %1;" : "=f"(r) : "f"(v)); return r;
}
// ---- packed f32x2 helpers ----
__device__ __forceinline__ u64 pk2(float lo, float hi) {
    u64 r; asm("mov.b64 %0, {%1, %2};" : "=l"(r) : "f"(lo), "f"(hi)); return r;
}
__device__ __forceinline__ void upk2(u64 v, float& lo, float& hi) {
    asm("mov.b64 {%0, %1}, %2;" : "=f"(lo), "=f"(hi) : "l"(v));
}
__device__ __forceinline__ u64 fma2(u64 a, u64 b, u64 c) {
    u64 d; asm("fma.rn.f32x2 %0, %1, %2, %3;" : "=l"(d) : "l"(a), "l"(b), "l"(c)); return d;
}
__device__ __forceinline__ u64 add2(u64 a, u64 b) {
    u64 d; asm("add.rn.f32x2 %0, %1, %2;" : "=l"(d) : "l"(a), "l"(b)); return d;
}
__device__ __forceinline__ u64 mul2(u64 a, u64 b) {
    u64 d; asm("mul.rn.f32x2 %0, %1, %2;" : "=l"(d) : "l"(a), "l"(b)); return d;
}

// LayerNorm one row of 256 floats, one warp.
__device__ __forceinline__ void ln_row_warp(const float* __restrict__ src,
                                            float* __restrict__ dst,
                                            const float* __restrict__ g,
                                            const float* __restrict__ be,
                                            int lane) {
    float4 a = ((const float4*)src)[lane];
    float4 c = ((const float4*)src)[lane + 32];
    float s = a.x + a.y + a.z + a.w + c.x + c.y + c.z + c.w;
    float q = a.x * a.x + a.y * a.y + a.z * a.z + a.w * a.w
            + c.x * c.x + c.y * c.y + c.z * c.z + c.w * c.w;
    s = warp_sum(s);
    q = warp_sum(q);
    float mu = s * (1.0f / 256.0f);
    float var = q * (1.0f / 256.0f) - mu * mu;
    float rs = rsqrtf(var + 1e-5f);
    float4 g0 = ((const float4*)g)[lane], g1 = ((const float4*)g)[lane + 32];
    float4 e0 = ((const float4*)be)[lane], e1 = ((const float4*)be)[lane + 32];
    float4 o0, o1;
    o0.x = (a.x - mu) * rs * g0.x + e0.x;
    o0.y = (a.y - mu) * rs * g0.y + e0.y;
    o0.z = (a.z - mu) * rs * g0.z + e0.z;
    o0.w = (a.w - mu) * rs * g0.w + e0.w;
    o1.x = (c.x - mu) * rs * g1.x + e1.x;
    o1.y = (c.y - mu) * rs * g1.y + e1.y;
    o1.z = (c.z - mu) * rs * g1.z + e1.z;
    o1.w = (c.w - mu) * rs * g1.w + e1.w;
    ((float4*)dst)[lane] = o0;
    ((float4*)dst)[lane + 32] = o1;
}

// Staged GEMM: acc[s] += sum_d inp[s*D+d] * W[row_off + r][d] for output r = tid.
// W row-major with row stride 256. Tiles of 16 d-values staged into smem
// (transposed, coalesced loads, conflict-free reads), visiting order rotated
// by block to decorrelate L2 line accesses across lock-stepped blocks.
__device__ __forceinline__ void gemm4_staged(const float* __restrict__ W, int row_off,
                                             const float* __restrict__ inp,
                                             float* __restrict__ tile,
                                             int tid, int bid, float acc[4]) {
    int c = tid & 15, r0 = tid >> 4;
    int t0 = bid & 15;
    float ld[16];
    {
        int d0 = t0 * 16;
        const float* Wp = W + (size_t)(row_off + r0) * 256 + d0 + c;
        #pragma unroll
        for (int i = 0; i < 16; i++) ld[i] = Wp[(size_t)i * 16 * 256];
    }
    for (int t = 0; t < 16; t++) {
        __syncthreads();
        #pragma unroll
        for (int i = 0; i < 16; i++) tile[c * 257 + r0 + i * 16] = ld[i];
        __syncthreads();
        int d0c = ((t0 + t) & 15) * 16;
        if (t + 1 < 16) {
            int d0n = ((t0 + t + 1) & 15) * 16;
            const float* Wp = W + (size_t)(row_off + r0) * 256 + d0n + c;
            #pragma unroll
            for (int i = 0; i < 16; i++) ld[i] = Wp[(size_t)i * 16 * 256];
        }
        #pragma unroll
        for (int dd = 0; dd < 16; dd++) {
            float wv = tile[dd * 257 + tid];
            #pragma unroll
            for (int s = 0; s < 4; s++) acc[s] = fmaf(inp[s * D + d0c + dd], wv, acc[s]);
        }
    }
}

// ---------------- slots init ----------------
__global__ __launch_bounds__(256) void init_slots_kernel(const float* __restrict__ noise,
                                                         const float* __restrict__ mu,
                                                         const float* __restrict__ ls) {
    int i = blockIdx.x * 256 + threadIdx.x;
    int d = i & (D - 1);
    g_slots[i] = mu[d] + noise[i] * expf(ls[d]);
}

// ---------------- qproj tail: g_qg, g_cm for 4 slots ----------------
__device__ __forceinline__ void qproj_tail(const float* fin, float* sln, float* qb,
                                           float* tile, float* red,
                                           int b, int sb, int tid, int bid,
                                           const float* __restrict__ Wq,
                                           const float* __restrict__ Wk,
                                           const float* __restrict__ g_sl,
                                           const float* __restrict__ be_sl,
                                           const float* __restrict__ gin) {
    int w = tid >> 5, lane = tid & 31;
    if (w < 4) ln_row_warp(fin + w * D, sln + w * D, g_sl, be_sl, lane);
    __syncthreads();
    // q[s][e=tid] = sum_d sln[s][d] * Wq[e][d]  (staged)
    float acc[4] = {0.f, 0.f, 0.f, 0.f};
    gemm4_staged(Wq, 0, sln, tile, tid, bid, acc);
    #pragma unroll
    for (int s = 0; s < 4; s++) qb[s * D + tid] = acc[s];
    __syncthreads();
    // qt[s][d=tid] = sum_e q[s][e] * Wk[e][d]  (coalesced, rotated start)
    float a2[4] = {0.f, 0.f, 0.f, 0.f};
    int e0 = (bid * 16) & 255;
    #pragma unroll 4
    for (int i = 0; i < D; i++) {
        int e = (e0 + i) & 255;
        float wv = Wk[(size_t)e * D + tid];
        #pragma unroll
        for (int s = 0; s < 4; s++) a2[s] += qb[s * D + e] * wv;
    }
    float gv = gin[tid];
    float nrm[4];
    #pragma unroll
    for (int s = 0; s < 4; s++) {
        float qv = a2[s] * SC_LOG2E * gv;
        g_qg[(b * S + sb + s) * D + tid] = qv;
        nrm[s] = qv * qv;
    }
    #pragma unroll
    for (int s = 0; s < 4; s++) {
        float v = warp_sum(nrm[s]);
        if (lane == 0) red[s * 8 + w] = v;
    }
    __syncthreads();
    if (tid < 4) {
        float t = 0.f;
        #pragma unroll
        for (int i = 0; i < 8; i++) t += red[tid * 8 + i];
        g_cm[b * S + sb + tid] = -16.0f * sqrtf(t);
    }
}

__global__ __launch_bounds__(256) void qproj0_kernel(const float* __restrict__ Wq,
                                                     const float* __restrict__ Wk,
                                                     const float* __restrict__ g_sl,
                                                     const float* __restrict__ be_sl,
                                                     const float* __restrict__ gin) {
    __shared__ __align__(16) float fin[4 * D], sln[4 * D], qb[4 * D];
    __shared__ __align__(16) float tile[16 * 257];
    __shared__ float red[32];
    int bid = blockIdx.x;
    int b = bid >> 1, sb = (bid & 1) * 4, tid = threadIdx.x;
    for (int i = tid; i < 4 * D; i += 256) fin[i] = g_slots[b * S * D + sb * D + i];
    __syncthreads();
    qproj_tail(fin, sln, qb, tile, red, b, sb, tid, bid, Wq, Wk, g_sl, be_sl, gin);
}

// ---------------- fused flash attention (warp-autonomous, f32x2, 2-row ILP) ----------------
__global__ __launch_bounds__(128, 2) void fused_attn_kernel(const float* __restrict__ x) {
    __shared__ __align__(16) float Usm[4 * S * D];
    __shared__ __align__(16) float hssm[4 * D];
    __shared__ float zsm[4 * S];
    int b = blockIdx.y;
    int wid = threadIdx.x >> 5, lane = threadIdx.x & 31;
    int pidx = blockIdx.x * 4 + wid;
    const float* xb = x + ((size_t)b * N + (size_t)pidx * RPW) * D + lane * 8;

    u64 qg2[S][4];
    #pragma unroll
    for (int s = 0; s < S; s++) {
        float4 a = *(const float4*)&g_qg[(b * S + s) * D + lane * 8];
        float4 c = *(const float4*)&g_qg[(b * S + s) * D + lane * 8 + 4];
        qg2[s][0] = pk2(a.x, a.y); qg2[s][1] = pk2(a.z, a.w);
        qg2[s][2] = pk2(c.x, c.y); qg2[s][3] = pk2(c.z, c.w);
    }
    float cm[S];
    #pragma unroll
    for (int s = 0; s < S; s++) cm[s] = g_cm[b * S + s];

    u64 U2[S][4];
    u64 zero2 = pk2(0.f, 0.f);
    #pragma unroll
    for (int s = 0; s < S; s++)
        #pragma unroll
        for (int k = 0; k < 4; k++) U2[s][k] = zero2;
    u64 hs2[4] = {zero2, zero2, zero2, zero2};
    float z[S];
    #pragma unroll
    for (int s = 0; s < S; s++) z[s] = 0.f;

    float4 pA0 = *(const float4*)xb;
    float4 pA1 = *(const float4*)(xb + 4);
    float4 pB0 = *(const float4*)(xb + D);
    float4 pB1 = *(const float4*)(xb + D + 4);

    for (int it = 0; it < RPW / 2; it++) {
        u64 xA[4] = {pk2(pA0.x, pA0.y), pk2(pA0.z, pA0.w),
                     pk2(pA1.x, pA1.y), pk2(pA1.z, pA1.w)};
        u64 xB[4] = {pk2(pB0.x, pB0.y), pk2(pB0.z, pB0.w),
                     pk2(pB1.x, pB1.y), pk2(pB1.z, pB1.w)};
        if (it + 1 < RPW / 2) {
            const float* nx = xb + (size_t)(2 * it + 2) * D;
            pA0 = *(const float4*)nx;
            pA1 = *(const float4*)(nx + 4);
            pB0 = *(const float4*)(nx + D);
            pB1 = *(const float4*)(nx + D + 4);
        }
        // LN sums (two independent chains)
        u64 s1pA = xA[0], s2pA = mul2(xA[0], xA[0]);
        u64 s1pB = xB[0], s2pB = mul2(xB[0], xB[0]);
        #pragma unroll
        for (int k = 1; k < 4; k++) {
            s1pA = add2(s1pA, xA[k]); s2pA = fma2(xA[k], xA[k], s2pA);
            s1pB = add2(s1pB, xB[k]); s2pB = fma2(xB[k], xB[k], s2pB);
        }
        float t0, t1;
        upk2(s1pA, t0, t1); float s1A = t0 + t1;
        upk2(s2pA, t0, t1); float s2A = t0 + t1;
        upk2(s1pB, t0, t1); float s1B = t0 + t1;
        upk2(s2pB, t0, t1); float s2B = t0 + t1;
        #pragma unroll
        for (int o = 16; o > 0; o >>= 1) {
            s1A += __shfl_xor_sync(0xffffffffu, s1A, o);
            s2A += __shfl_xor_sync(0xffffffffu, s2A, o);
            s1B += __shfl_xor_sync(0xffffffffu, s1B, o);
            s2B += __shfl_xor_sync(0xffffffffu, s2B, o);
        }
        float muA = s1A * (1.0f / 256.0f);
        float rsA = rsqrtf(fmaf(-muA, muA, s2A * (1.0f / 256.0f)) + 1e-5f);
        float nbA = -muA * rsA;
        float muB = s1B * (1.0f / 256.0f);
        float rsB = rsqrtf(fmaf(-muB, muB, s2B * (1.0f / 256.0f)) + 1e-5f);
        float nbB = -muB * rsB;
        u64 rsA2 = pk2(rsA, rsA), nbA2 = pk2(nbA, nbA);
        u64 rsB2 = pk2(rsB, rsB), nbB2 = pk2(nbB, nbB);
        u64 hA[4], hB[4];
        #pragma unroll
        for (int k = 0; k < 4; k++) {
            hA[k] = fma2(xA[k], rsA2, nbA2);
            hB[k] = fma2(xB[k], rsB2, nbB2);
        }
        // logits partials (two rows)
        float pA[S], pB[S];
        #pragma unroll
        for (int s = 0; s < S; s++) {
            u64 a = mul2(qg2[s][0], hA[0]);
            u64 c = mul2(qg2[s][0], hB[0]);
            #pragma unroll
            for (int k = 1; k < 4; k++) {
                a = fma2(qg2[s][k], hA[k], a);
                c = fma2(qg2[s][k], hB[k], c);
            }
            upk2(a, t0, t1); pA[s] = t0 + t1;
            upk2(c, t0, t1); pB[s] = t0 + t1;
        }
        #pragma unroll
        for (int o = 16; o > 0; o >>= 1) {
            #pragma unroll
            for (int s = 0; s < S; s++) {
                pA[s] += __shfl_xor_sync(0xffffffffu, pA[s], o);
                pB[s] += __shfl_xor_sync(0xffffffffu, pB[s], o);
            }
        }
        #pragma unroll
        for (int s = 0; s < S; s++) {
            float wA = ex2f(pA[s] + cm[s]);
            float wB = ex2f(pB[s] + cm[s]);
            z[s] += wA + wB;
            u64 wA2 = pk2(wA, wA), wB2 = pk2(wB, wB);
            #pragma unroll
            for (int k = 0; k < 4; k++) {
                U2[s][k] = fma2(wA2, hA[k], U2[s][k]);
                U2[s][k] = fma2(wB2, hB[k], U2[s][k]);
            }
        }
        #pragma unroll
        for (int k = 0; k < 4; k++) hs2[k] = add2(hs2[k], add2(hA[k], hB[k]));
    }

    // block merge
    #pragma unroll
    for (int s = 0; s < S; s++) {
        float u0, u1, u2v, u3, u4, u5, u6, u7;
        upk2(U2[s][0], u0, u1); upk2(U2[s][1], u2v, u3);
        upk2(U2[s][2], u4, u5); upk2(U2[s][3], u6, u7);
        *(float4*)&Usm[(wid * S + s) * D + lane * 8] = make_float4(u0, u1, u2v, u3);
        *(float4*)&Usm[(wid * S + s) * D + lane * 8 + 4] = make_float4(u4, u5, u6, u7);
    }
    {
        float h0, h1, h2v, h3, h4, h5, h6, h7;
        upk2(hs2[0], h0, h1); upk2(hs2[1], h2v, h3);
        upk2(hs2[2], h4, h5); upk2(hs2[3], h6, h7);
        *(float4*)&hssm[wid * D + lane * 8] = make_float4(h0, h1, h2v, h3);
        *(float4*)&hssm[wid * D + lane * 8 + 4] = make_float4(h4, h5, h6, h7);
    }
    if (lane == 0) {
        #pragma unroll
        for (int s = 0; s < S; s++) zsm[wid * S + s] = z[s];
    }
    __syncthreads();
    int tid = threadIdx.x;
    size_t pb = (size_t)blockIdx.x * B + b;
    #pragma unroll
    for (int k = 0; k < S; k++) {
        float a = 0.f, a2 = 0.f;
        #pragma unroll
        for (int w = 0; w < 4; w++) {
            a += Usm[(w * S + k) * D + tid];
            a2 += Usm[(w * S + k) * D + tid + 128];
        }
        g_Up[(pb * S + k) * D + tid] = a;
        g_Up[(pb * S + k) * D + tid + 128] = a2;
    }
    {
        float a = 0.f, a2 = 0.f;
        #pragma unroll
        for (int w = 0; w < 4; w++) { a += hssm[w * D + tid]; a2 += hssm[w * D + tid + 128]; }
        g_hs[pb * D + tid] = a;
        g_hs[pb * D + tid + 128] = a2;
    }
    if (tid < S) {
        float a = 0.f;
        #pragma unroll
        for (int w = 0; w < 4; w++) a += zsm[w * S + tid];
        g_z[pb * S + tid] = a;
    }
}

// ---------------- fused epilogue: reduce + GRU + MLP + next qproj ----------------
__global__ __launch_bounds__(256) void iter_kernel(
    const float* __restrict__ gin, const float* __restrict__ bein,
    const float* __restrict__ Wv,
    const float* __restrict__ Wih, const float* __restrict__ Whh,
    const float* __restrict__ bih, const float* __restrict__ bhh,
    const float* __restrict__ W1, const float* __restrict__ b1,
    const float* __restrict__ W2, const float* __restrict__ b2,
    const float* __restrict__ g_ff, const float* __restrict__ be_ff,
    const float* __restrict__ g_sl, const float* __restrict__ be_sl,
    const float* __restrict__ Wq, const float* __restrict__ Wk,
    float* __restrict__ out, int last) {
    __shared__ __align__(16) float upd[4 * D], prev[4 * D], uv[4 * D];
    __shared__ __align__(16) float fin[4 * D], sln[4 * D], qb[4 * D];
    __shared__ __align__(16) float tile[16 * 257];
    __shared__ float red[32];
    __shared__ float zin[4];
    int bid = blockIdx.x;
    int b = bid >> 1, sb = (bid & 1) * 4, tid = threadIdx.x;
    int w = tid >> 5, lane = tid & 31;

    // ---- reduce partials -> updates (x-space), fold LN-out affine ----
    float ua[4] = {0.f, 0.f, 0.f, 0.f};
    #pragma unroll
    for (int p = 0; p < NP; p++) {
        size_t base = ((size_t)p * B + b) * S * D + sb * D;
        #pragma unroll
        for (int s = 0; s < 4; s++) ua[s] += g_Up[base + s * D + tid];
    }
    float hsum = 0.f;
    #pragma unroll
    for (int p = 0; p < NP; p++) hsum += g_hs[((size_t)p * B + b) * D + tid];
    if (tid < 4) {
        float zz = 0.f;
        #pragma unroll
        for (int p = 0; p < NP; p++) zz += g_z[(p * B + b) * S + sb + tid];
        zin[tid] = 1.f / zz;
    }
    for (int i = tid; i < 4 * D; i += 256) prev[i] = g_slots[b * S * D + sb * D + i];
    __syncthreads();
    const float rn = 1.f / (1.f + (float)N * 1e-8f);
    float gv = gin[tid], bv = bein[tid];
    #pragma unroll
    for (int s = 0; s < 4; s++)
        upd[s * D + tid] = gv * ((ua[s] * zin[s] + 1e-8f * hsum) * rn) + bv;
    __syncthreads();
    // ---- uv = updates @ Wv^T (staged) ----
    {
        float acc[4] = {0.f, 0.f, 0.f, 0.f};
        gemm4_staged(Wv, 0, upd, tile, tid, bid, acc);
        __syncthreads();
        #pragma unroll
        for (int s = 0; s < 4; s++) uv[s * D + tid] = acc[s];
    }
    __syncthreads();
    // ---- GRU (staged; 3 gates x 2 matrices) ----
    {
        float ai0[4] = {0,0,0,0}, ai1[4] = {0,0,0,0}, ai2[4] = {0,0,0,0};
        float ah0[4] = {0,0,0,0}, ah1[4] = {0,0,0,0}, ah2[4] = {0,0,0,0};
        gemm4_staged(Wih, 0,   uv,   tile, tid, bid, ai0);
        gemm4_staged(Wih, 256, uv,   tile, tid, bid, ai1);
        gemm4_staged(Wih, 512, uv,   tile, tid, bid, ai2);
        gemm4_staged(Whh, 0,   prev, tile, tid, bid, ah0);
        gemm4_staged(Whh, 256, prev, tile, tid, bid, ah1);
        gemm4_staged(Whh, 512, prev, tile, tid, bid, ah2);
        float bi0 = bih[tid], bi1 = bih[D + tid], bi2 = bih[2 * D + tid];
        float bh0 = bhh[tid], bh1 = bhh[D + tid], bh2 = bhh[2 * D + tid];
        __syncthreads();
        #pragma unroll
        for (int s = 0; s < 4; s++) {
            float r = 1.f / (1.f + expf(-(ai0[s] + bi0 + ah0[s] + bh0)));
            float zz = 1.f / (1.f + expf(-(ai1[s] + bi1 + ah1[s] + bh1)));
            float nn = tanhf(ai2[s] + bi2 + r * (ah2[s] + bh2));
            fin[s * D + tid] = (1.f - zz) * nn + zz * prev[s * D + tid];
        }
    }
    __syncthreads();
    // ---- MLP + residual ----
    if (w < 4) ln_row_warp(fin + w * D, sln + w * D, g_ff, be_ff, lane);
    __syncthreads();
    {
        float acc[4] = {0.f, 0.f, 0.f, 0.f};
        gemm4_staged(W1, 0, sln, tile, tid, bid, acc);
        float b1v = b1[tid];
        __syncthreads();
        #pragma unroll
        for (int s = 0; s < 4; s++) qb[s * D + tid] = fmaxf(acc[s] + b1v, 0.f);
    }
    __syncthreads();
    {
        float a2[4] = {0.f, 0.f, 0.f, 0.f};
        gemm4_staged(W2, 0, qb, tile, tid, bid, a2);
        float b2v = b2[tid];
        __syncthreads();
        #pragma unroll
        for (int s = 0; s < 4; s++) {
            float o = fin[s * D + tid] + a2[s] + b2v;
            fin[s * D + tid] = o;
            g_slots[b * S * D + sb * D + s * D + tid] = o;
            if (last) out[b * S * D + sb * D + s * D + tid] = o;
        }
    }
    __syncthreads();
    if (!last)
        qproj_tail(fin, sln, qb, tile, red, b, sb, tid, bid, Wq, Wk, g_sl, be_sl, gin);
}

extern "C" void kernel_launch(void* const* d_in, const int* in_sizes, int n_in,
                              void* d_out, int out_size) {
    const float* x        = (const float*)d_in[0];
    const float* noise    = (const float*)d_in[1];
    const float* slots_mu = (const float*)d_in[2];
    const float* slots_ls = (const float*)d_in[3];
    const float* Wq       = (const float*)d_in[4];
    const float* Wk       = (const float*)d_in[5];
    const float* Wv       = (const float*)d_in[6];
    const float* W_ih     = (const float*)d_in[7];
    const float* W_hh     = (const float*)d_in[8];
    const float* b_ih     = (const float*)d_in[9];
    const float* b_hh     = (const float*)d_in[10];
    const float* W1       = (const float*)d_in[11];
    const float* b1       = (const float*)d_in[12];
    const float* W2       = (const float*)d_in[13];
    const float* b2       = (const float*)d_in[14];
    const float* g_in     = (const float*)d_in[15];
    const float* be_in    = (const float*)d_in[16];
    const float* g_sl     = (const float*)d_in[17];
    const float* be_sl    = (const float*)d_in[18];
    const float* g_ff     = (const float*)d_in[19];
    const float* be_ff    = (const float*)d_in[20];
    float* out = (float*)d_out;

    init_slots_kernel<<<(B * S * D) / 256, 256>>>(noise, slots_mu, slots_ls);
    qproj0_kernel<<<B * 2, 256>>>(Wq, Wk, g_sl, be_sl, g_in);
    for (int it = 0; it < 3; it++) {
        fused_attn_kernel<<<dim3(NP, B), 128>>>(x);
        iter_kernel<<<B * 2, 256>>>(g_in, be_in, Wv, W_ih, W_hh, b_ih, b_hh,
                                    W1, b1, W2, b2, g_ff, be_ff, g_sl, be_sl,
                                    Wq, Wk, out, it == 2 ? 1 : 0);
    }
}